// round 7
// baseline (speedup 1.0000x reference)
#include <cuda_runtime.h>
#include <cstdint>
#include <math.h>

#define B_   16
#define N_   1024
#define P_   8
#define H_   300
#define HP_  320
#define MT   128
#define NC   64
#define NCT  5
#define KB   32      // int8 k-elems per chunk
#define NKT  10      // 320/32

#define QMAXF 16256.0f   // 127*128

// ---------------- device-global scratch ----------------
__device__ __align__(16) int8_t g_Aq[2ull * B_ * N_ * P_ * HP_];  // 84 MB (hi|lo)
__device__ __align__(16) int8_t g_Wq[2ull * P_ * HP_ * HP_];      // 1.6 MB
__device__ float g_sA[B_ * N_ * P_];
__device__ float g_sB[P_ * HP_];
__device__ float g_partial[NCT * B_ * N_];

#define LIMBA ((size_t)B_ * N_ * P_ * HP_)
#define LIMBW ((size_t)P_ * HP_ * HP_)

// ---------------- helpers ----------------
__device__ __forceinline__ float warp_sum(float v) {
#pragma unroll
    for (int o = 16; o; o >>= 1) v += __shfl_xor_sync(0xffffffffu, v, o);
    return v;
}
__device__ __forceinline__ float warp_max(float v) {
#pragma unroll
    for (int o = 16; o; o >>= 1) v = fmaxf(v, __shfl_xor_sync(0xffffffffu, v, o));
    return v;
}
__device__ __forceinline__ uint32_t smem_u32(const void* p) {
    uint32_t a;
    asm("{ .reg .u64 t; cvta.to.shared.u64 t, %1; cvt.u32.u64 %0, t; }" : "=r"(a) : "l"(p));
    return a;
}
__device__ __forceinline__ void cpa16(uint32_t dst, const void* src) {
    asm volatile("cp.async.cg.shared.global [%0], [%1], 16;" :: "r"(dst), "l"(src));
}
#define CPA_COMMIT() asm volatile("cp.async.commit_group;")

__device__ __forceinline__ void ldm4(uint32_t* r, uint32_t a) {
    asm volatile("ldmatrix.sync.aligned.m8n8.x4.shared.b16 {%0,%1,%2,%3}, [%4];"
                 : "=r"(r[0]), "=r"(r[1]), "=r"(r[2]), "=r"(r[3]) : "r"(a));
}
__device__ __forceinline__ void mma_s8(int* c, const uint32_t* a, const uint32_t* b) {
    asm("mma.sync.aligned.m16n8k32.row.col.s32.s8.s8.s32 "
        "{%0,%1,%2,%3},{%4,%5,%6,%7},{%8,%9},{%0,%1,%2,%3};"
        : "+r"(c[0]), "+r"(c[1]), "+r"(c[2]), "+r"(c[3])
        : "r"(a[0]), "r"(a[1]), "r"(a[2]), "r"(a[3]), "r"(b[0]), "r"(b[1]));
}

// ===========================================================================
// K1: quantize W^T: per (p,ko) row over h, 14-bit 2-limb int8 + f32 scale
// ===========================================================================
__global__ void prep_w(const float* __restrict__ W) {
    int t = blockIdx.x * blockDim.x + threadIdx.x;
    if (t >= P_ * HP_) return;
    int p = t / HP_, ko = t % HP_;
    float amax = 0.f;
    if (ko < H_)
        for (int h = 0; h < H_; h++)
            amax = fmaxf(amax, fabsf(W[((size_t)p * H_ + h) * H_ + ko]));
    float inv = amax > 0.f ? QMAXF / amax : 0.f;
    g_sB[t] = amax > 0.f ? amax / QMAXF : 1.f;
    size_t base = (size_t)t * HP_;
    for (int h4 = 0; h4 < HP_ / 4; h4++) {
        uint32_t hw = 0, lw = 0;
#pragma unroll
        for (int e = 0; e < 4; e++) {
            int h = h4 * 4 + e;
            float w = (ko < H_ && h < H_) ? W[((size_t)p * H_ + h) * H_ + ko] : 0.f;
            int q = __float2int_rn(w * inv);
            int hi = (q + 64) >> 7;
            int lo = q - (hi << 7);
            hw |= ((uint32_t)(uint8_t)(int8_t)hi) << (8 * e);
            lw |= ((uint32_t)(uint8_t)(int8_t)lo) << (8 * e);
        }
        *(uint32_t*)(g_Wq + base + h4 * 4) = hw;
        *(uint32_t*)(g_Wq + LIMBW + base + h4 * 4) = lw;
    }
}

// ===========================================================================
// K2: quantize A: one warp per (b,n,p) row; fold instruction; 2-limb int8
// ===========================================================================
__global__ __launch_bounds__(256)
void prep_a(const float* __restrict__ na, const float* __restrict__ instr) {
    int gw = (blockIdx.x * blockDim.x + threadIdx.x) >> 5;
    int lane = threadIdx.x & 31;
    if (gw >= B_ * N_ * P_) return;
    int b = gw >> 13;
    const float* src = na + (size_t)gw * H_;
    const float* ib  = instr + b * H_;
    float v[10];
    float amax = 0.f;
#pragma unroll
    for (int j = 0; j < 10; j++) {
        int idx = lane + 32 * j;
        float x = (idx < H_) ? src[idx] * ib[idx] : 0.f;
        v[j] = x;
        amax = fmaxf(amax, fabsf(x));
    }
    amax = warp_max(amax);
    float inv = amax > 0.f ? QMAXF / amax : 0.f;
    if (lane == 0) g_sA[gw] = amax > 0.f ? amax / QMAXF : 1.f;
    size_t base = (size_t)gw * HP_;
#pragma unroll
    for (int j = 0; j < 10; j++) {
        int idx = lane + 32 * j;
        int q = __float2int_rn(v[j] * inv);
        int hi = (q + 64) >> 7;
        int lo = q - (hi << 7);
        g_Aq[base + idx] = (int8_t)hi;
        g_Aq[LIMBA + base + idx] = (int8_t)lo;
    }
}

// ===========================================================================
// K3: FUSED int8 2-limb GEMM over all 8 p + sim fold + normalize + elu + wss
// grid (NCT, N/MT, B) = (5, 8, 16) = 640; 256 thr = 8 warps (4m x 2n), 32x32
// smem/stage: Ahi 128x48B | Alo | Bhi 64x48B | Blo = 18432 B; x3 stages
// ===========================================================================
#define RSTR  48
#define A_T   (128 * RSTR)
#define Bt_T  (64 * RSTR)
#define STG   (2 * A_T + 2 * Bt_T)   // 18432
#define OAL   A_T
#define OBH   (2 * A_T)
#define NSTG  3

__global__ __launch_bounds__(256)
void fused_gemm(const float* __restrict__ sim, const float* __restrict__ wss) {
    extern __shared__ char smraw[];
    const uint32_t sbase = smem_u32(smraw);
    __shared__ float ssim[P_];
    __shared__ float swss[NC];
    __shared__ float red[2][MT];

    const int t = threadIdx.x, lane = t & 31, wid = t >> 5;
    const int g = lane >> 2, tq = lane & 3;
    const int b = blockIdx.z, m0 = blockIdx.y * MT, n0 = blockIdx.x * NC;
    const int wm = wid & 3, wn = wid >> 2;
    const int m_w = wm * 32, n_w = wn * 32;

    if (t < P_) ssim[t] = sim[b * P_ + t];
    if (t < NC) swss[t] = (n0 + t < H_) ? wss[n0 + t] : 0.f;

    // cp.async indexing
    const int arow = t >> 1, aseg = t & 1;
    const int brow = t >> 2, blimb = (t >> 1) & 1, bseg = t & 1;
    // ldmatrix lane offsets (validated R4/R6 geometry)
    const uint32_t aoff = (uint32_t)((lane & 15) * RSTR + ((lane >> 4) << 4));
    const uint32_t boff = (uint32_t)((((lane & 7) + ((lane >> 4) << 3)) * RSTR) +
                                     (((lane >> 3) & 1) << 4));

    auto issue = [&](int p, int kt, int s) {
        const uint32_t st = sbase + s * STG;
        {
            const int kh = kt * KB + aseg * 16;
            const uint32_t so = (uint32_t)(arow * RSTR + aseg * 16);
            size_t ga = ((size_t)((b * N_ + m0 + arow) * P_) + p) * HP_ + kh;
            cpa16(st + so, g_Aq + ga);
            cpa16(st + OAL + so, g_Aq + LIMBA + ga);
        }
        {
            const int kh = kt * KB + bseg * 16;
            const uint32_t so = (uint32_t)(brow * RSTR + bseg * 16);
            size_t gb = ((size_t)p * HP_ + n0 + brow) * HP_ + kh;
            cpa16(st + OBH + blimb * Bt_T + so, g_Wq + blimb * LIMBW + gb);
        }
    };

    float sacc[2][4][4], qacc[2][4][4];
#pragma unroll
    for (int mf = 0; mf < 2; mf++)
#pragma unroll
        for (int nf = 0; nf < 4; nf++)
#pragma unroll
            for (int e = 0; e < 4; e++) { sacc[mf][nf][e] = 0.f; qacc[mf][nf][e] = 0.f; }

    issue(0, 0, 0); CPA_COMMIT();
    issue(0, 1, 1); CPA_COMMIT();
    __syncthreads();   // ssim/swss visible

    // issue-target counters (2 ahead)
    int ip = 0, ik = 2;
    int st_idx = 2;    // stage for next issue

#pragma unroll 1
    for (int p = 0; p < P_; p++) {
        int chh[2][4][4], cmd[2][4][4];
#pragma unroll
        for (int mf = 0; mf < 2; mf++)
#pragma unroll
            for (int nf = 0; nf < 4; nf++)
#pragma unroll
                for (int e = 0; e < 4; e++) { chh[mf][nf][e] = 0; cmd[mf][nf][e] = 0; }

#pragma unroll 1
        for (int kt = 0; kt < NKT; kt++) {
            const int it = p * NKT + kt;
            const int s = it % NSTG;
            asm volatile("cp.async.wait_group 1;");
            __syncthreads();
            if (ip < P_) {
                issue(ip, ik, st_idx);
                if (++ik == NKT) { ik = 0; ip++; }
                if (++st_idx == NSTG) st_idx = 0;
            }
            CPA_COMMIT();

            const uint32_t st = sbase + s * STG;
            uint32_t ah[2][4], al[2][4], bh[2][4], blr[2][4];
#pragma unroll
            for (int mf = 0; mf < 2; mf++) {
                uint32_t ba = st + (uint32_t)((m_w + mf * 16) * RSTR) + aoff;
                ldm4(ah[mf], ba);
                ldm4(al[mf], ba + OAL);
            }
#pragma unroll
            for (int nfp = 0; nfp < 2; nfp++) {
                uint32_t bb = st + OBH + (uint32_t)((n_w + nfp * 16) * RSTR) + boff;
                ldm4(bh[nfp], bb);
                ldm4(blr[nfp], bb + Bt_T);
            }
#pragma unroll
            for (int mf = 0; mf < 2; mf++)
#pragma unroll
                for (int nf = 0; nf < 4; nf++) {
                    const uint32_t* ph = &bh[nf >> 1][(nf & 1) * 2];
                    const uint32_t* pl = &blr[nf >> 1][(nf & 1) * 2];
                    mma_s8(chh[mf][nf], ah[mf], ph);   // hi*hi  (<<14)
                    mma_s8(cmd[mf][nf], ah[mf], pl);   // hi*lo  (<<7)
                    mma_s8(cmd[mf][nf], al[mf], ph);   // lo*hi  (<<7)
                }
        }

        // ---- per-p: recombine limbs, apply scales & sim, fold into s/q ----
        {
            const float sp = ssim[p];
            float sa[2][2];
#pragma unroll
            for (int mf = 0; mf < 2; mf++)
#pragma unroll
                for (int hh = 0; hh < 2; hh++) {
                    int row = m0 + m_w + mf * 16 + g + hh * 8;
                    sa[mf][hh] = sp * g_sA[(b * N_ + row) * P_ + p];
                }
#pragma unroll
            for (int mf = 0; mf < 2; mf++)
#pragma unroll
                for (int nf = 0; nf < 4; nf++) {
                    int gc = n0 + n_w + nf * 8 + 2 * tq;
                    float2 sb2 = *(const float2*)(g_sB + p * HP_ + gc);
#pragma unroll
                    for (int e = 0; e < 4; e++) {
                        float v = (float)chh[mf][nf][e] * 16384.f +
                                  (float)cmd[mf][nf][e] * 128.f;
                        float sv = v * sa[mf][e >> 1] * ((e & 1) ? sb2.y : sb2.x);
                        sacc[mf][nf][e] += sv;
                        qacc[mf][nf][e] = fmaf(sv, sv, qacc[mf][nf][e]);
                    }
                }
        }
    }

    // ---- final epilogue: normalize over P, elu, *wss, row-reduce ----
    float rr[2][2] = {{0.f, 0.f}, {0.f, 0.f}};
#pragma unroll
    for (int mf = 0; mf < 2; mf++)
#pragma unroll
        for (int nf = 0; nf < 4; nf++)
#pragma unroll
            for (int e = 0; e < 4; e++) {
                int col = n_w + nf * 8 + 2 * tq + (e & 1);
                float nrm = fmaxf(sqrtf(qacc[mf][nf][e]), 1e-12f);
                float sc  = sacc[mf][nf][e] / nrm;
                float el  = sc > 0.f ? sc : expm1f(sc);
                rr[mf][e >> 1] += el * swss[col];
            }
#pragma unroll
    for (int mf = 0; mf < 2; mf++)
#pragma unroll
        for (int hh = 0; hh < 2; hh++) {
            rr[mf][hh] += __shfl_xor_sync(0xffffffffu, rr[mf][hh], 1);
            rr[mf][hh] += __shfl_xor_sync(0xffffffffu, rr[mf][hh], 2);
        }
    if (tq == 0) {
#pragma unroll
        for (int mf = 0; mf < 2; mf++)
#pragma unroll
            for (int hh = 0; hh < 2; hh++)
                red[wn][m_w + mf * 16 + hh * 8 + g] = rr[mf][hh];
    }
    __syncthreads();
    if (t < MT)
        g_partial[((size_t)blockIdx.x * B_ + b) * N_ + m0 + t] = red[0][t] + red[1][t];
}

// ===========================================================================
// K4: combine partials + mask, softmax over N per batch
// ===========================================================================
__global__ __launch_bounds__(1024)
void softmax_kernel(const float* __restrict__ mask, float* __restrict__ out) {
    const int b = blockIdx.x, t = threadIdx.x;
    float v = mask[b * N_ + t];
#pragma unroll
    for (int i = 0; i < NCT; i++) v += g_partial[((size_t)i * B_ + b) * N_ + t];

    __shared__ float red[32];
    const int lane = t & 31, wid = t >> 5;

    float m = warp_max(v);
    if (lane == 0) red[wid] = m;
    __syncthreads();
    if (wid == 0) red[lane] = warp_max(red[lane]);
    __syncthreads();
    m = red[0];
    __syncthreads();

    float e = expf(v - m);
    float s = warp_sum(e);
    if (lane == 0) red[wid] = s;
    __syncthreads();
    if (wid == 0) red[lane] = warp_sum(red[lane]);
    __syncthreads();
    s = red[0];

    out[b * N_ + t] = e / s;
}

// ===========================================================================
extern "C" void kernel_launch(void* const* d_in, const int* in_sizes, int n_in,
                              void* d_out, int out_size) {
    const float* node_attr = (const float*)d_in[0];
    const float* instr     = (const float*)d_in[2];
    const float* sim       = (const float*)d_in[4];
    const float* mask      = (const float*)d_in[5];
    const float* W         = (const float*)d_in[6];
    const float* wss       = (const float*)d_in[7];
    float* out = (float*)d_out;

    cudaFuncSetAttribute(fused_gemm, cudaFuncAttributeMaxDynamicSharedMemorySize,
                         NSTG * STG);

    prep_w<<<(P_ * HP_ + 255) / 256, 256>>>(W);

    const int nwarps = B_ * N_ * P_;
    prep_a<<<nwarps / 8, 256>>>(node_attr, instr);

    dim3 gg(NCT, N_ / MT, B_);    // (5, 8, 16)
    fused_gemm<<<gg, 256, NSTG * STG>>>(sim, wss);

    softmax_kernel<<<B_, 1024>>>(mask, out);
}

// round 8
// speedup vs baseline: 1.3135x; 1.3135x over previous
#include <cuda_runtime.h>
#include <cstdint>
#include <math.h>

#define B_   16
#define N_   1024
#define P_   8
#define H_   300
#define HP_  320
#define MT   128
#define NC   64
#define NCT  5
#define KB   64      // int8 k-elems per chunk (2 mma k-steps)
#define NKT  5       // 320/64

#define QMAXF 16256.0f   // 127*128

// ---------------- device-global scratch ----------------
__device__ __align__(16) int8_t g_Aq[2ull * B_ * N_ * P_ * HP_];  // 84 MB (hi|lo)
__device__ __align__(16) int8_t g_Wq[2ull * P_ * HP_ * HP_];      // 1.6 MB
__device__ float g_sA[B_ * N_ * P_];
__device__ float g_sB[P_ * HP_];
__device__ float g_Y[(size_t)B_ * P_ * N_ * HP_];                 // 168 MB
__device__ float g_logits[B_ * N_];

#define LIMBA ((size_t)B_ * N_ * P_ * HP_)
#define LIMBW ((size_t)P_ * HP_ * HP_)

// ---------------- helpers ----------------
__device__ __forceinline__ float warp_sum(float v) {
#pragma unroll
    for (int o = 16; o; o >>= 1) v += __shfl_xor_sync(0xffffffffu, v, o);
    return v;
}
__device__ __forceinline__ float warp_max(float v) {
#pragma unroll
    for (int o = 16; o; o >>= 1) v = fmaxf(v, __shfl_xor_sync(0xffffffffu, v, o));
    return v;
}
__device__ __forceinline__ uint32_t smem_u32(const void* p) {
    uint32_t a;
    asm("{ .reg .u64 t; cvta.to.shared.u64 t, %1; cvt.u32.u64 %0, t; }" : "=r"(a) : "l"(p));
    return a;
}
__device__ __forceinline__ void cpa16(uint32_t dst, const void* src) {
    asm volatile("cp.async.cg.shared.global [%0], [%1], 16;" :: "r"(dst), "l"(src));
}
#define CPA_COMMIT() asm volatile("cp.async.commit_group;")

__device__ __forceinline__ void ldm4(uint32_t* r, uint32_t a) {
    asm volatile("ldmatrix.sync.aligned.m8n8.x4.shared.b16 {%0,%1,%2,%3}, [%4];"
                 : "=r"(r[0]), "=r"(r[1]), "=r"(r[2]), "=r"(r[3]) : "r"(a));
}
__device__ __forceinline__ void mma_s8(int* c, const uint32_t* a, const uint32_t* b) {
    asm("mma.sync.aligned.m16n8k32.row.col.s32.s8.s8.s32 "
        "{%0,%1,%2,%3},{%4,%5,%6,%7},{%8,%9},{%0,%1,%2,%3};"
        : "+r"(c[0]), "+r"(c[1]), "+r"(c[2]), "+r"(c[3])
        : "r"(a[0]), "r"(a[1]), "r"(a[2]), "r"(a[3]), "r"(b[0]), "r"(b[1]));
}

// ===========================================================================
// K1: quantize W^T: per (p,ko) row over h, 14-bit 2-limb int8 + f32 scale
// ===========================================================================
__global__ void prep_w(const float* __restrict__ W) {
    int t = blockIdx.x * blockDim.x + threadIdx.x;
    if (t >= P_ * HP_) return;
    int p = t / HP_, ko = t % HP_;
    float amax = 0.f;
    if (ko < H_)
        for (int h = 0; h < H_; h++)
            amax = fmaxf(amax, fabsf(W[((size_t)p * H_ + h) * H_ + ko]));
    float inv = amax > 0.f ? QMAXF / amax : 0.f;
    g_sB[t] = amax > 0.f ? amax / QMAXF : 1.f;
    size_t base = (size_t)t * HP_;
    for (int h4 = 0; h4 < HP_ / 4; h4++) {
        uint32_t hw = 0, lw = 0;
#pragma unroll
        for (int e = 0; e < 4; e++) {
            int h = h4 * 4 + e;
            float w = (ko < H_ && h < H_) ? W[((size_t)p * H_ + h) * H_ + ko] : 0.f;
            int q = __float2int_rn(w * inv);
            int hi = (q + 64) >> 7;
            int lo = q - (hi << 7);
            hw |= ((uint32_t)(uint8_t)(int8_t)hi) << (8 * e);
            lw |= ((uint32_t)(uint8_t)(int8_t)lo) << (8 * e);
        }
        *(uint32_t*)(g_Wq + base + h4 * 4) = hw;
        *(uint32_t*)(g_Wq + LIMBW + base + h4 * 4) = lw;
    }
}

// ===========================================================================
// K2: quantize A: one warp per (b,n,p) row; fold instruction; 2-limb int8
// ===========================================================================
__global__ __launch_bounds__(256)
void prep_a(const float* __restrict__ na, const float* __restrict__ instr) {
    int gw = (blockIdx.x * blockDim.x + threadIdx.x) >> 5;
    int lane = threadIdx.x & 31;
    if (gw >= B_ * N_ * P_) return;
    int b = gw >> 13;
    const float* src = na + (size_t)gw * H_;
    const float* ib  = instr + b * H_;
    float v[10];
    float amax = 0.f;
#pragma unroll
    for (int j = 0; j < 10; j++) {
        int idx = lane + 32 * j;
        float x = (idx < H_) ? src[idx] * ib[idx] : 0.f;
        v[j] = x;
        amax = fmaxf(amax, fabsf(x));
    }
    amax = warp_max(amax);
    float inv = amax > 0.f ? QMAXF / amax : 0.f;
    if (lane == 0) g_sA[gw] = amax > 0.f ? amax / QMAXF : 1.f;
    size_t base = (size_t)gw * HP_;
#pragma unroll
    for (int j = 0; j < 10; j++) {
        int idx = lane + 32 * j;
        int q = __float2int_rn(v[j] * inv);
        int hi = (q + 64) >> 7;
        int lo = q - (hi << 7);
        g_Aq[base + idx] = (int8_t)hi;
        g_Aq[LIMBA + base + idx] = (int8_t)lo;
    }
}

// ===========================================================================
// K3: batched int8 2-limb GEMM, KB=64 chunks, 3-stage cp.async, 1 sync/chunk
// grid (NCT, N/MT, B*P) = (5, 8, 128); 256 thr = 8 warps (4m x 2n), warp 32x32
// smem/stage: Ahi 128x80B | Alo | Bhi 64x80B | Blo = 30720 B; x3 = 92160 B
// ===========================================================================
#define RSTR  80
#define A_T   (128 * RSTR)          // 10240
#define Bt_T  (64 * RSTR)           // 5120
#define STG   (2 * A_T + 2 * Bt_T)  // 30720
#define OAL   A_T
#define OBH   (2 * A_T)
#define NSTG  3

__global__ __launch_bounds__(256, 2)
void gemm() {
    extern __shared__ char smraw[];
    const uint32_t sbase = smem_u32(smraw);

    const int t = threadIdx.x, lane = t & 31, wid = t >> 5;
    const int g = lane >> 2, tq = lane & 3;
    const int bp = blockIdx.z, b = bp >> 3, p = bp & 7;
    const int m0 = blockIdx.y * MT, n0 = blockIdx.x * NC;
    const int wm = wid & 3, wn = wid >> 2;
    const int m_w = wm * 32, n_w = wn * 32;

    // cp.async indexing: A rows 128 x 4 segs (x2 via i); B rows 64 x 4 segs x 2 limbs
    const int arow0 = t >> 2, aseg = t & 3;     // + i*64 rows
    const int brow = t >> 2, bseg = t & 3;
    // ldmatrix lane offsets (proven geometry, stride-parametric)
    const uint32_t aoff = (uint32_t)((lane & 15) * RSTR + ((lane >> 4) << 4));
    const uint32_t boff = (uint32_t)((((lane & 7) + ((lane >> 4) << 3)) * RSTR) +
                                     (((lane >> 3) & 1) << 4));

    auto issue = [&](int kt, int s) {
        const uint32_t st = sbase + s * STG;
        const int kh = kt * KB + aseg * 16;
#pragma unroll
        for (int i = 0; i < 2; i++) {
            const int row = arow0 + i * 64;
            const uint32_t so = (uint32_t)(row * RSTR + aseg * 16);
            size_t ga = ((size_t)((b * N_ + m0 + row) * P_) + p) * HP_ + kh;
            cpa16(st + so, g_Aq + ga);
            cpa16(st + OAL + so, g_Aq + LIMBA + ga);
        }
        {
            const uint32_t so = (uint32_t)(brow * RSTR + bseg * 16);
            size_t gb = ((size_t)p * HP_ + n0 + brow) * HP_ + kh;
            cpa16(st + OBH + so, g_Wq + gb);
            cpa16(st + OBH + Bt_T + so, g_Wq + LIMBW + gb);
        }
    };

    int chh[2][4][4], cmd[2][4][4];
#pragma unroll
    for (int mf = 0; mf < 2; mf++)
#pragma unroll
        for (int nf = 0; nf < 4; nf++)
#pragma unroll
            for (int e = 0; e < 4; e++) { chh[mf][nf][e] = 0; cmd[mf][nf][e] = 0; }

    issue(0, 0); CPA_COMMIT();
    issue(1, 1); CPA_COMMIT();

#pragma unroll 1
    for (int kt = 0; kt < NKT; kt++) {
        const int s = kt % NSTG;
        asm volatile("cp.async.wait_group 1;");
        __syncthreads();
        if (kt + 2 < NKT) issue(kt + 2, (kt + 2) % NSTG);
        CPA_COMMIT();

        const uint32_t st = sbase + s * STG;
#pragma unroll
        for (int ks = 0; ks < 2; ks++) {
            const uint32_t kkb = (uint32_t)(ks * 32);
            uint32_t ah[2][4], al[2][4], bh[2][4], blr[2][4];
#pragma unroll
            for (int mf = 0; mf < 2; mf++) {
                uint32_t ba = st + (uint32_t)((m_w + mf * 16) * RSTR) + kkb + aoff;
                ldm4(ah[mf], ba);
                ldm4(al[mf], ba + OAL);
            }
#pragma unroll
            for (int nfp = 0; nfp < 2; nfp++) {
                uint32_t bb = st + OBH + (uint32_t)((n_w + nfp * 16) * RSTR) + kkb + boff;
                ldm4(bh[nfp], bb);
                ldm4(blr[nfp], bb + Bt_T);
            }
#pragma unroll
            for (int mf = 0; mf < 2; mf++)
#pragma unroll
                for (int nf = 0; nf < 4; nf++) {
                    const uint32_t* ph = &bh[nf >> 1][(nf & 1) * 2];
                    const uint32_t* pl = &blr[nf >> 1][(nf & 1) * 2];
                    mma_s8(chh[mf][nf], ah[mf], ph);   // hi*hi (<<14)
                    mma_s8(cmd[mf][nf], ah[mf], pl);   // hi*lo (<<7)
                    mma_s8(cmd[mf][nf], al[mf], ph);   // lo*hi (<<7)
                }
        }
    }

    // ---- apply scales, store Y ----
    float sa[2][2];
#pragma unroll
    for (int mf = 0; mf < 2; mf++)
#pragma unroll
        for (int hh = 0; hh < 2; hh++) {
            int row = m0 + m_w + mf * 16 + g + hh * 8;
            sa[mf][hh] = g_sA[(b * N_ + row) * P_ + p];
        }

    float* yb = g_Y + (size_t)(b * P_ + p) * N_ * HP_;
#pragma unroll
    for (int mf = 0; mf < 2; mf++)
#pragma unroll
        for (int nf = 0; nf < 4; nf++) {
            int gr = m0 + m_w + mf * 16 + g;
            int gc = n0 + n_w + nf * 8 + 2 * tq;
            float2 sb2 = *(const float2*)(g_sB + p * HP_ + gc);
            float v0 = (float)chh[mf][nf][0] * 16384.f + (float)cmd[mf][nf][0] * 128.f;
            float v1 = (float)chh[mf][nf][1] * 16384.f + (float)cmd[mf][nf][1] * 128.f;
            float v2 = (float)chh[mf][nf][2] * 16384.f + (float)cmd[mf][nf][2] * 128.f;
            float v3 = (float)chh[mf][nf][3] * 16384.f + (float)cmd[mf][nf][3] * 128.f;
            *(float2*)(yb + (size_t)gr * HP_ + gc) =
                make_float2(sa[mf][0] * sb2.x * v0, sa[mf][0] * sb2.y * v1);
            *(float2*)(yb + (size_t)(gr + 8) * HP_ + gc) =
                make_float2(sa[mf][1] * sb2.x * v2, sa[mf][1] * sb2.y * v3);
        }
}

// ===========================================================================
// K4: per-(b,n) row, ONE WARP each: sv=sim_p*y; normalize over P; elu; wss dot
// grid = B_*N_/8 blocks of 256 (8 warps)
// ===========================================================================
__global__ __launch_bounds__(256)
void epilogue(const float* __restrict__ sim,
              const float* __restrict__ wss,
              const float* __restrict__ mask) {
    const int gw = (blockIdx.x * blockDim.x + threadIdx.x) >> 5;  // b*N + n
    const int lane = threadIdx.x & 31;
    const int b = gw >> 10, n = gw & 1023;
    const float* base = g_Y + ((size_t)b * P_ * N_ + n) * HP_;

    float sp[P_];
#pragma unroll
    for (int p = 0; p < P_; p++) sp[p] = sim[b * P_ + p];

    float acc = 0.f;
#pragma unroll
    for (int j = 0; j < 10; j++) {
        int k = lane + 32 * j;
        if (k < H_) {
            float s = 0.f, q = 0.f;
#pragma unroll
            for (int p = 0; p < P_; p++) {
                float v = sp[p] * base[(size_t)p * (N_ * HP_) + k];
                s += v;
                q = fmaf(v, v, q);
            }
            float nrm = fmaxf(sqrtf(q), 1e-12f);
            float sc  = s / nrm;
            float e   = sc > 0.f ? sc : expm1f(sc);
            acc += e * wss[k];
        }
    }
    acc = warp_sum(acc);
    if (lane == 0) g_logits[gw] = acc + mask[gw];
}

// ===========================================================================
// K5: softmax over N per batch
// ===========================================================================
__global__ __launch_bounds__(1024)
void softmax_kernel(float* __restrict__ out) {
    const int b = blockIdx.x, t = threadIdx.x;
    float v = g_logits[b * N_ + t];
    __shared__ float red[32];
    const int lane = t & 31, wid = t >> 5;

    float m = warp_max(v);
    if (lane == 0) red[wid] = m;
    __syncthreads();
    if (wid == 0) red[lane] = warp_max(red[lane]);
    __syncthreads();
    m = red[0];
    __syncthreads();

    float e = expf(v - m);
    float s = warp_sum(e);
    if (lane == 0) red[wid] = s;
    __syncthreads();
    if (wid == 0) red[lane] = warp_sum(red[lane]);
    __syncthreads();
    s = red[0];

    out[b * N_ + t] = e / s;
}

// ===========================================================================
extern "C" void kernel_launch(void* const* d_in, const int* in_sizes, int n_in,
                              void* d_out, int out_size) {
    const float* node_attr = (const float*)d_in[0];
    const float* instr     = (const float*)d_in[2];
    const float* sim       = (const float*)d_in[4];
    const float* mask      = (const float*)d_in[5];
    const float* W         = (const float*)d_in[6];
    const float* wss       = (const float*)d_in[7];
    float* out = (float*)d_out;

    cudaFuncSetAttribute(gemm, cudaFuncAttributeMaxDynamicSharedMemorySize, NSTG * STG);

    prep_w<<<(P_ * HP_ + 255) / 256, 256>>>(W);

    const int nwarps = B_ * N_ * P_;
    prep_a<<<nwarps / 8, 256>>>(node_attr, instr);

    dim3 gg(NCT, N_ / MT, B_ * P_);   // (5, 8, 128)
    gemm<<<gg, 256, NSTG * STG>>>();

    epilogue<<<(B_ * N_) / 8, 256>>>(sim, wss, mask);

    softmax_kernel<<<B_, 1024>>>(out);
}

// round 9
// speedup vs baseline: 1.3208x; 1.0056x over previous
#include <cuda_runtime.h>
#include <cstdint>
#include <math.h>

#define B_   16
#define N_   1024
#define P_   8
#define H_   300
#define HP_  320
#define MT   128
#define NC   64
#define NCT  5
#define KB   64      // int8 k-elems per chunk (2 mma k-steps)
#define NKT  5       // 320/64

#define QMAXF 16256.0f   // 127*128

// ---------------- device-global scratch ----------------
__device__ __align__(16) int8_t g_Aq[2ull * B_ * N_ * P_ * HP_];  // 84 MB (hi|lo)
__device__ __align__(16) int8_t g_Wq[2ull * P_ * HP_ * HP_];      // 1.6 MB
__device__ float g_sA[B_ * N_ * P_];
__device__ float g_sB[P_ * HP_];
__device__ float g_Y[(size_t)B_ * P_ * N_ * HP_];                 // 168 MB
__device__ float g_logits[B_ * N_];

#define LIMBA ((size_t)B_ * N_ * P_ * HP_)
#define LIMBW ((size_t)P_ * HP_ * HP_)

// ---------------- helpers ----------------
__device__ __forceinline__ float warp_sum(float v) {
#pragma unroll
    for (int o = 16; o; o >>= 1) v += __shfl_xor_sync(0xffffffffu, v, o);
    return v;
}
__device__ __forceinline__ float warp_max(float v) {
#pragma unroll
    for (int o = 16; o; o >>= 1) v = fmaxf(v, __shfl_xor_sync(0xffffffffu, v, o));
    return v;
}
__device__ __forceinline__ uint32_t smem_u32(const void* p) {
    uint32_t a;
    asm("{ .reg .u64 t; cvta.to.shared.u64 t, %1; cvt.u32.u64 %0, t; }" : "=r"(a) : "l"(p));
    return a;
}
__device__ __forceinline__ void cpa16(uint32_t dst, const void* src) {
    asm volatile("cp.async.cg.shared.global [%0], [%1], 16;" :: "r"(dst), "l"(src));
}
#define CPA_COMMIT() asm volatile("cp.async.commit_group;")

__device__ __forceinline__ void ldm4(uint32_t* r, uint32_t a) {
    asm volatile("ldmatrix.sync.aligned.m8n8.x4.shared.b16 {%0,%1,%2,%3}, [%4];"
                 : "=r"(r[0]), "=r"(r[1]), "=r"(r[2]), "=r"(r[3]) : "r"(a));
}
__device__ __forceinline__ void mma_s8(int* c, const uint32_t* a, const uint32_t* b) {
    asm("mma.sync.aligned.m16n8k32.row.col.s32.s8.s8.s32 "
        "{%0,%1,%2,%3},{%4,%5,%6,%7},{%8,%9},{%0,%1,%2,%3};"
        : "+r"(c[0]), "+r"(c[1]), "+r"(c[2]), "+r"(c[3])
        : "r"(a[0]), "r"(a[1]), "r"(a[2]), "r"(a[3]), "r"(b[0]), "r"(b[1]));
}

// ===========================================================================
// K1: quantize W^T: per (p,ko) row over h, 14-bit 2-limb int8 + f32 scale
// ===========================================================================
__global__ void prep_w(const float* __restrict__ W) {
    int t = blockIdx.x * blockDim.x + threadIdx.x;
    if (t >= P_ * HP_) return;
    int p = t / HP_, ko = t % HP_;
    float amax = 0.f;
    if (ko < H_)
        for (int h = 0; h < H_; h++)
            amax = fmaxf(amax, fabsf(W[((size_t)p * H_ + h) * H_ + ko]));
    float inv = amax > 0.f ? QMAXF / amax : 0.f;
    g_sB[t] = amax > 0.f ? amax / QMAXF : 1.f;
    size_t base = (size_t)t * HP_;
    for (int h4 = 0; h4 < HP_ / 4; h4++) {
        uint32_t hw = 0, lw = 0;
#pragma unroll
        for (int e = 0; e < 4; e++) {
            int h = h4 * 4 + e;
            float w = (ko < H_ && h < H_) ? W[((size_t)p * H_ + h) * H_ + ko] : 0.f;
            int q = __float2int_rn(w * inv);
            int hi = (q + 64) >> 7;
            int lo = q - (hi << 7);
            hw |= ((uint32_t)(uint8_t)(int8_t)hi) << (8 * e);
            lw |= ((uint32_t)(uint8_t)(int8_t)lo) << (8 * e);
        }
        *(uint32_t*)(g_Wq + base + h4 * 4) = hw;
        *(uint32_t*)(g_Wq + LIMBW + base + h4 * 4) = lw;
    }
}

// ===========================================================================
// K2: quantize A: one warp per (b,n,p) row; vectorized word stores
// lane handles word w = j*32+lane (4 consecutive k), j = 0..2
// ===========================================================================
__global__ __launch_bounds__(256)
void prep_a(const float* __restrict__ na, const float* __restrict__ instr) {
    int gw = (blockIdx.x * blockDim.x + threadIdx.x) >> 5;
    int lane = threadIdx.x & 31;
    if (gw >= B_ * N_ * P_) return;
    int b = gw >> 13;
    const float* src = na + (size_t)gw * H_;
    const float* ib  = instr + b * H_;

    float4 v[3];
    float amax = 0.f;
#pragma unroll
    for (int j = 0; j < 3; j++) {
        int w = j * 32 + lane;          // word index; k = 4w
        int k = w * 4;
        float4 x = make_float4(0.f, 0.f, 0.f, 0.f);
        if (k < H_) {                   // H_ % 4 == 0, no straddle
            x = *(const float4*)(src + k);
            x.x *= ib[k]; x.y *= ib[k + 1]; x.z *= ib[k + 2]; x.w *= ib[k + 3];
        }
        v[j] = x;
        amax = fmaxf(amax, fmaxf(fmaxf(fabsf(x.x), fabsf(x.y)),
                                 fmaxf(fabsf(x.z), fabsf(x.w))));
    }
    amax = warp_max(amax);
    float inv = amax > 0.f ? QMAXF / amax : 0.f;
    if (lane == 0) g_sA[gw] = amax > 0.f ? amax / QMAXF : 1.f;

    size_t base = (size_t)gw * HP_;
#pragma unroll
    for (int j = 0; j < 3; j++) {
        int w = j * 32 + lane;
        if (w < HP_ / 4) {
            uint32_t hw = 0, lw = 0;
            const float* xe = (const float*)&v[j];
#pragma unroll
            for (int e = 0; e < 4; e++) {
                int q = __float2int_rn(xe[e] * inv);
                int hi = (q + 64) >> 7;
                int lo = q - (hi << 7);
                hw |= ((uint32_t)(uint8_t)(int8_t)hi) << (8 * e);
                lw |= ((uint32_t)(uint8_t)(int8_t)lo) << (8 * e);
            }
            *(uint32_t*)(g_Aq + base + w * 4) = hw;
            *(uint32_t*)(g_Aq + LIMBA + base + w * 4) = lw;
        }
    }
}

// ===========================================================================
// K3: batched int8 2-limb GEMM, B-RESIDENT smem + 3-stage A pipeline
// grid (NCT, N/MT, B*P) = (5, 8, 128); 256 thr = 8 warps (4m x 2n), warp 32x32
// smem: A 3 stages x [Ahi 128x80B | Alo] = 61440 | B resident 2 x 64x336B = 43008
// ===========================================================================
#define RSTR  80
#define A_T   (128 * RSTR)          // 10240
#define ASTG  (2 * A_T)             // 20480 per A stage
#define OAL   A_T
#define NSTG  3
#define BSTR  336                   // B-resident row stride (320 data + 16 pad)
#define Bt_R  (64 * BSTR)           // 21504 per limb
#define OB    (NSTG * ASTG)         // 61440
#define SMEM_TOT (OB + 2 * Bt_R)    // 104448

__global__ __launch_bounds__(256, 2)
void gemm() {
    extern __shared__ char smraw[];
    const uint32_t sbase = smem_u32(smraw);

    const int t = threadIdx.x, lane = t & 31, wid = t >> 5;
    const int g = lane >> 2, tq = lane & 3;
    const int bp = blockIdx.z, b = bp >> 3, p = bp & 7;
    const int m0 = blockIdx.y * MT, n0 = blockIdx.x * NC;
    const int wm = wid & 3, wn = wid >> 2;
    const int m_w = wm * 32, n_w = wn * 32;

    // A cp.async indexing: 128 rows x 4 16B segs (x2 limbs), 2 rows per thread
    const int arow0 = t >> 2, aseg = t & 3;
    // ldmatrix lane offsets (proven geometry; stride-parametric)
    const uint32_t aoff = (uint32_t)((lane & 15) * RSTR + ((lane >> 4) << 4));
    const uint32_t boff = (uint32_t)((((lane & 7) + ((lane >> 4) << 3)) * BSTR) +
                                     (((lane >> 3) & 1) << 4));

    auto issueA = [&](int kt, int s) {
        const uint32_t st = sbase + s * ASTG;
        const int kh = kt * KB + aseg * 16;
#pragma unroll
        for (int i = 0; i < 2; i++) {
            const int row = arow0 + i * 64;
            const uint32_t so = (uint32_t)(row * RSTR + aseg * 16);
            size_t ga = ((size_t)((b * N_ + m0 + row) * P_) + p) * HP_ + kh;
            cpa16(st + so, g_Aq + ga);
            cpa16(st + OAL + so, g_Aq + LIMBA + ga);
        }
    };

    // ---- B resident load: 64 rows x 320 B x 2 limbs ----
    {
#pragma unroll
        for (int limb = 0; limb < 2; limb++) {
            const int8_t* gb0 = g_Wq + (size_t)limb * LIMBW;
            const uint32_t sb0 = sbase + OB + limb * Bt_R;
#pragma unroll
            for (int i = 0; i < 5; i++) {
                int u = t + i * 256;          // 0..1279
                int row = u / 20, seg = u % 20;
                cpa16(sb0 + row * BSTR + seg * 16,
                      gb0 + ((size_t)p * HP_ + n0 + row) * HP_ + seg * 16);
            }
        }
    }
    issueA(0, 0); CPA_COMMIT();     // group0: B + A0
    issueA(1, 1); CPA_COMMIT();     // group1: A1

    int chh[2][4][4], cmd[2][4][4];
#pragma unroll
    for (int mf = 0; mf < 2; mf++)
#pragma unroll
        for (int nf = 0; nf < 4; nf++)
#pragma unroll
            for (int e = 0; e < 4; e++) { chh[mf][nf][e] = 0; cmd[mf][nf][e] = 0; }

#pragma unroll 1
    for (int kt = 0; kt < NKT; kt++) {
        const int s = kt % NSTG;
        asm volatile("cp.async.wait_group 1;");
        __syncthreads();
        if (kt + 2 < NKT) issueA(kt + 2, (kt + 2) % NSTG);
        CPA_COMMIT();

        const uint32_t st = sbase + s * ASTG;
        const uint32_t bbase = sbase + OB + (uint32_t)(kt * KB);
#pragma unroll
        for (int ks = 0; ks < 2; ks++) {
            const uint32_t kkb = (uint32_t)(ks * 32);
            uint32_t ah[2][4], al[2][4], bh[2][4], blr[2][4];
#pragma unroll
            for (int mf = 0; mf < 2; mf++) {
                uint32_t ba = st + (uint32_t)((m_w + mf * 16) * RSTR) + kkb + aoff;
                ldm4(ah[mf], ba);
                ldm4(al[mf], ba + OAL);
            }
#pragma unroll
            for (int nfp = 0; nfp < 2; nfp++) {
                uint32_t bb = bbase + (uint32_t)((n_w + nfp * 16) * BSTR) + kkb + boff;
                ldm4(bh[nfp], bb);
                ldm4(blr[nfp], bb + Bt_R);
            }
#pragma unroll
            for (int mf = 0; mf < 2; mf++)
#pragma unroll
                for (int nf = 0; nf < 4; nf++) {
                    const uint32_t* ph = &bh[nf >> 1][(nf & 1) * 2];
                    const uint32_t* pl = &blr[nf >> 1][(nf & 1) * 2];
                    mma_s8(chh[mf][nf], ah[mf], ph);   // hi*hi (<<14)
                    mma_s8(cmd[mf][nf], ah[mf], pl);   // hi*lo (<<7)
                    mma_s8(cmd[mf][nf], al[mf], ph);   // lo*hi (<<7)
                }
        }
    }

    // ---- apply scales, store Y ----
    float sa[2][2];
#pragma unroll
    for (int mf = 0; mf < 2; mf++)
#pragma unroll
        for (int hh = 0; hh < 2; hh++) {
            int row = m0 + m_w + mf * 16 + g + hh * 8;
            sa[mf][hh] = g_sA[(b * N_ + row) * P_ + p];
        }

    float* yb = g_Y + (size_t)(b * P_ + p) * N_ * HP_;
#pragma unroll
    for (int mf = 0; mf < 2; mf++)
#pragma unroll
        for (int nf = 0; nf < 4; nf++) {
            int gr = m0 + m_w + mf * 16 + g;
            int gc = n0 + n_w + nf * 8 + 2 * tq;
            float2 sb2 = *(const float2*)(g_sB + p * HP_ + gc);
            float v0 = (float)chh[mf][nf][0] * 16384.f + (float)cmd[mf][nf][0] * 128.f;
            float v1 = (float)chh[mf][nf][1] * 16384.f + (float)cmd[mf][nf][1] * 128.f;
            float v2 = (float)chh[mf][nf][2] * 16384.f + (float)cmd[mf][nf][2] * 128.f;
            float v3 = (float)chh[mf][nf][3] * 16384.f + (float)cmd[mf][nf][3] * 128.f;
            *(float2*)(yb + (size_t)gr * HP_ + gc) =
                make_float2(sa[mf][0] * sb2.x * v0, sa[mf][0] * sb2.y * v1);
            *(float2*)(yb + (size_t)(gr + 8) * HP_ + gc) =
                make_float2(sa[mf][1] * sb2.x * v2, sa[mf][1] * sb2.y * v3);
        }
}

// ===========================================================================
// K4: per-(b,n) row, one warp each: sv=sim_p*y; normalize over P; elu; wss dot
// ===========================================================================
__global__ __launch_bounds__(256)
void epilogue(const float* __restrict__ sim,
              const float* __restrict__ wss,
              const float* __restrict__ mask) {
    const int gw = (blockIdx.x * blockDim.x + threadIdx.x) >> 5;  // b*N + n
    const int lane = threadIdx.x & 31;
    const int b = gw >> 10, n = gw & 1023;
    const float* base = g_Y + ((size_t)b * P_ * N_ + n) * HP_;

    float sp[P_];
#pragma unroll
    for (int p = 0; p < P_; p++) sp[p] = sim[b * P_ + p];

    float acc = 0.f;
#pragma unroll
    for (int j = 0; j < 10; j++) {
        int k = lane + 32 * j;
        if (k < H_) {
            float s = 0.f, q = 0.f;
#pragma unroll
            for (int p = 0; p < P_; p++) {
                float v = sp[p] * base[(size_t)p * (N_ * HP_) + k];
                s += v;
                q = fmaf(v, v, q);
            }
            float nrm = fmaxf(sqrtf(q), 1e-12f);
            float sc  = s / nrm;
            float e   = sc > 0.f ? sc : expm1f(sc);
            acc += e * wss[k];
        }
    }
    acc = warp_sum(acc);
    if (lane == 0) g_logits[gw] = acc + mask[gw];
}

// ===========================================================================
// K5: softmax over N per batch
// ===========================================================================
__global__ __launch_bounds__(1024)
void softmax_kernel(float* __restrict__ out) {
    const int b = blockIdx.x, t = threadIdx.x;
    float v = g_logits[b * N_ + t];
    __shared__ float red[32];
    const int lane = t & 31, wid = t >> 5;

    float m = warp_max(v);
    if (lane == 0) red[wid] = m;
    __syncthreads();
    if (wid == 0) red[lane] = warp_max(red[lane]);
    __syncthreads();
    m = red[0];
    __syncthreads();

    float e = expf(v - m);
    float s = warp_sum(e);
    if (lane == 0) red[wid] = s;
    __syncthreads();
    if (wid == 0) red[lane] = warp_sum(red[lane]);
    __syncthreads();
    s = red[0];

    out[b * N_ + t] = e / s;
}

// ===========================================================================
extern "C" void kernel_launch(void* const* d_in, const int* in_sizes, int n_in,
                              void* d_out, int out_size) {
    const float* node_attr = (const float*)d_in[0];
    const float* instr     = (const float*)d_in[2];
    const float* sim       = (const float*)d_in[4];
    const float* mask      = (const float*)d_in[5];
    const float* W         = (const float*)d_in[6];
    const float* wss       = (const float*)d_in[7];
    float* out = (float*)d_out;

    cudaFuncSetAttribute(gemm, cudaFuncAttributeMaxDynamicSharedMemorySize, SMEM_TOT);

    prep_w<<<(P_ * HP_ + 255) / 256, 256>>>(W);

    const int nwarps = B_ * N_ * P_;
    prep_a<<<nwarps / 8, 256>>>(node_attr, instr);

    dim3 gg(NCT, N_ / MT, B_ * P_);   // (5, 8, 128)
    gemm<<<gg, 256, SMEM_TOT>>>();

    epilogue<<<(B_ * N_) / 8, 256>>>(sim, wss, mask);

    softmax_kernel<<<B_, 1024>>>(out);
}